// round 17
// baseline (speedup 1.0000x reference)
#include <cuda_runtime.h>
#include <cuda_fp16.h>
#include <cstdint>
#include <type_traits>

// Problem constants (fixed by setup_inputs)
#define N0 20000      // nodes
#define EE 640000     // edges
#define HH 128        // hidden
#define DD 3          // edge-attr dims
#define RR 8          // relations

#define TXSZ ((size_t)RR * N0 * HH)

// Scratch (static device globals; no allocation allowed)
__device__ __half   g_h0[(size_t)N0 * HH];        // 5.1 MB  (fp16)
__device__ __half   g_h1[(size_t)3 * N0 * HH];    // 15.4 MB (fp16)
__device__ __half   g_txh[3][TXSZ];               // 3 x 41 MB (per-j, enables overlap)
__device__ float    g_inv[DD * RR * N0];          // 1.9 MB
__device__ int      g_deg[N0];
__device__ int      g_off[N0];
__device__ int      g_pos[N0];
__device__ int      g_total;
__device__ uint32_t g_plj[3][EE];                 // 7.7 MB : per-j packed (r<<29)|src
__device__ __half2  g_wh[24 * 16 * 256];          // 393 KB : fp16 W, sW-interleaved

// ---------------------------------------------------------------------------
__device__ __forceinline__ void mma_f16(float* c, const uint32_t* a, const uint32_t* b) {
    asm volatile("mma.sync.aligned.m16n8k16.row.col.f32.f16.f16.f32 "
                 "{%0,%1,%2,%3},{%4,%5,%6,%7},{%8,%9},{%0,%1,%2,%3};"
                 : "+f"(c[0]), "+f"(c[1]), "+f"(c[2]), "+f"(c[3])
                 : "r"(a[0]), "r"(a[1]), "r"(a[2]), "r"(a[3]), "r"(b[0]), "r"(b[1]));
}

// ---------------------------------------------------------------------------
// Weight precompute: cw fp32 -> g_wh fp16, interleaved for direct sW copies.
// ---------------------------------------------------------------------------
__global__ void wcvt_kernel(const float* __restrict__ cw) {
    int idx = blockIdx.x * blockDim.x + threadIdx.x;
    if (idx >= 24 * 16 * 256) return;
    int col = idx & 255;           // r*32 + d
    int c2  = (idx >> 8) & 15;     // c-pair
    int ljb = idx >> 12;           // (l*3+j)*4 + b
    int b = ljb & 3, lj = ljb >> 2;
    int r = col >> 5, d = col & 31;
    size_t base = ((((size_t)(lj * 8 + r) * 4 + b) * 32 + 2 * c2) * 32) + d;
    g_wh[idx] = __floats2half2_rn(cw[base], cw[base + 32]);
}

// ---------------------------------------------------------------------------
// CSR build + inverse counts
// ---------------------------------------------------------------------------
__global__ void zero_kernel() {
    int i = blockIdx.x * blockDim.x + threadIdx.x;
    if (i < DD * RR * N0) g_inv[i] = 0.f;
    if (i == 0) g_total = 0;
}

__global__ void count_kernel(const int* __restrict__ ei, const int* __restrict__ ea) {
    int e = blockIdx.x * blockDim.x + threadIdx.x;
    if (e >= EE) return;
    int dd = ei[EE + e];
#pragma unroll
    for (int j = 0; j < DD; j++) {
        int r = ea[e * DD + j];
        atomicAdd(&g_inv[(j * RR + r) * N0 + dd], 1.0f);
    }
}

// runs BEFORE inv_kernel: derives deg from the j=0 relation counts
__global__ void offsets_kernel() {
    int d = blockIdx.x * blockDim.x + threadIdx.x;
    if (d >= N0) return;
    float s = 0.f;
#pragma unroll
    for (int r = 0; r < RR; r++) s += g_inv[r * N0 + d];
    int dg = (int)s;
    int o = atomicAdd(&g_total, dg);
    g_deg[d] = dg;
    g_off[d] = o;
    g_pos[d] = o;
}

__global__ void inv_kernel() {
    int i = blockIdx.x * blockDim.x + threadIdx.x;
    if (i < DD * RR * N0) {
        float c = g_inv[i];
        g_inv[i] = 1.0f / fmaxf(c, 1.0f);
    }
}

__global__ void fill_kernel(const int* __restrict__ ei, const int* __restrict__ ea) {
    int e = blockIdx.x * blockDim.x + threadIdx.x;
    if (e >= EE) return;
    uint32_t s = (uint32_t)ei[e];
    int dd = ei[EE + e];
    uint32_t r0 = (uint32_t)ea[e * DD + 0];
    uint32_t r1 = (uint32_t)ea[e * DD + 1];
    uint32_t r2 = (uint32_t)ea[e * DD + 2];
    int p = atomicAdd(&g_pos[dd], 1);
    g_plj[0][p] = (r0 << 29) | s;
    g_plj[1][p] = (r1 << 29) | s;
    g_plj[2][p] = (r2 << 29) | s;
}

// ---------------------------------------------------------------------------
// fp16 GEMM, 512 threads = 16 warps (4m x 4n), warp tile 32x32, block 128x128.
// out[M,128] = A[M,K] @ B[K,128] (+bias), relu for rows >= relu_from.
// 32 accумulators/thread -> ~60 regs -> 2 blocks/SM = 32 warps (2x latency hiding).
// ---------------------------------------------------------------------------
template <typename TA, typename TO>
__global__ void __launch_bounds__(512, 2)
gemm_f16(const TA* __restrict__ A, const float* __restrict__ B,
         const float* __restrict__ bias, TO* __restrict__ out,
         int M, int K, int relu_from) {
    __shared__ __half  sA[128][40];    // row stride 20 words: conflict-free frag reads
    __shared__ __half2 sB[16][136];    // sB[k/2][n]; row stride 136 words
    int m0   = blockIdx.x * 128;
    int wid  = threadIdx.x >> 5, lane = threadIdx.x & 31;
    int mw   = wid >> 2;            // 0..3 : 32-row slab
    int nw   = wid & 3;             // 0..3 : 32-col slab
    int gid  = lane >> 2;           // 0..7
    int qid  = lane & 3;            // 0..3

    float c[2][4][4];
#pragma unroll
    for (int mt = 0; mt < 2; mt++)
#pragma unroll
        for (int nt = 0; nt < 4; nt++)
#pragma unroll
            for (int q = 0; q < 4; q++) c[mt][nt][q] = 0.f;

    for (int k0 = 0; k0 < K; k0 += 32) {
        // A tile 128x32 -> half
        if constexpr (std::is_same<TA, float>::value) {
#pragma unroll
            for (int it = 0; it < 2; it++) {
                int idx = threadIdx.x + it * 512;
                int m = idx >> 3, k4 = (idx & 7) * 4;
                float4 v = make_float4(0.f, 0.f, 0.f, 0.f);
                if (m0 + m < M) v = *(const float4*)&A[(size_t)(m0 + m) * K + k0 + k4];
                *(__half2*)&sA[m][k4]     = __floats2half2_rn(v.x, v.y);
                *(__half2*)&sA[m][k4 + 2] = __floats2half2_rn(v.z, v.w);
            }
        } else {
            int idx = threadIdx.x;              // 512 = 128 rows x 4 uint4
            int m = idx >> 2, k8 = (idx & 3) * 8;
            uint4 v = make_uint4(0, 0, 0, 0);
            if (m0 + m < M) v = *(const uint4*)&A[(size_t)(m0 + m) * K + k0 + k8];
            *(uint2*)&sA[m][k8]     = make_uint2(v.x, v.y);
            *(uint2*)&sA[m][k8 + 4] = make_uint2(v.z, v.w);
        }
        // B tile 32x128 -> 16 k-pair rows x 128 half2 (512 idx exactly)
        {
            int idx = threadIdx.x;
            int r2 = idx >> 5, c4 = (idx & 31) * 4;
            float4 u = *(const float4*)&B[(size_t)(k0 + 2 * r2) * HH + c4];
            float4 w = *(const float4*)&B[(size_t)(k0 + 2 * r2 + 1) * HH + c4];
            sB[r2][c4 + 0] = __floats2half2_rn(u.x, w.x);
            sB[r2][c4 + 1] = __floats2half2_rn(u.y, w.y);
            sB[r2][c4 + 2] = __floats2half2_rn(u.z, w.z);
            sB[r2][c4 + 3] = __floats2half2_rn(u.w, w.w);
        }
        __syncthreads();
#pragma unroll
        for (int ks = 0; ks < 32; ks += 16) {
            uint32_t a[2][4], b[4][2];
#pragma unroll
            for (int mt = 0; mt < 2; mt++) {
                int r = mw * 32 + mt * 16 + gid;
                a[mt][0] = *(const uint32_t*)&sA[r][ks + qid * 2];
                a[mt][1] = *(const uint32_t*)&sA[r + 8][ks + qid * 2];
                a[mt][2] = *(const uint32_t*)&sA[r][ks + qid * 2 + 8];
                a[mt][3] = *(const uint32_t*)&sA[r + 8][ks + qid * 2 + 8];
            }
            int kp = ks >> 1;   // pair-row base: 0 or 8
#pragma unroll
            for (int nt = 0; nt < 4; nt++) {
                int cn = nw * 32 + nt * 8 + gid;
                b[nt][0] = *(const uint32_t*)&sB[kp + qid][cn];
                b[nt][1] = *(const uint32_t*)&sB[kp + qid + 4][cn];
            }
#pragma unroll
            for (int mt = 0; mt < 2; mt++)
#pragma unroll
                for (int nt = 0; nt < 4; nt++) mma_f16(c[mt][nt], a[mt], b[nt]);
        }
        __syncthreads();
    }

#pragma unroll
    for (int mt = 0; mt < 2; mt++) {
        int row0 = m0 + mw * 32 + mt * 16 + gid;
        int row1 = row0 + 8;
#pragma unroll
        for (int nt = 0; nt < 4; nt++) {
            int col = nw * 32 + nt * 8 + qid * 2;
            float b0 = bias ? bias[col] : 0.f;
            float b1 = bias ? bias[col + 1] : 0.f;
#pragma unroll
            for (int rr = 0; rr < 2; rr++) {
                int row = rr ? row1 : row0;
                if (row >= M) continue;
                float v0 = c[mt][nt][rr * 2 + 0] + b0;
                float v1 = c[mt][nt][rr * 2 + 1] + b1;
                if (row >= relu_from) { v0 = fmaxf(v0, 0.f); v1 = fmaxf(v1, 0.f); }
                if constexpr (std::is_same<TO, float>::value) {
                    *(float2*)&out[(size_t)row * HH + col] = make_float2(v0, v1);
                } else {
                    *(__half2*)&out[(size_t)row * HH + col] = __floats2half2_rn(v0, v1);
                }
            }
        }
    }
}

// ---------------------------------------------------------------------------
// fp16 tx, 512 threads = 16 warps (2m x 8n), warp tile 32x32, grid (N0/128, 4).
// Block loads its b-slice of W once (16KB), then two 64-node subtiles:
//   C[64 x 256] = h[:, 32b:32b+32] @ Wb[32 x 256]; staged 32-row coalesced out.
// Static smem: sA 5.1KB + sW 16.9KB + sC 16.9KB = 38.9KB; 2 blocks/SM = 32 warps.
// ---------------------------------------------------------------------------
__global__ void __launch_bounds__(512, 2)
tx_f16(const __half* __restrict__ h, const __half2* __restrict__ wh, __half* __restrict__ dst) {
    __shared__ __half  sA[64][40];
    __shared__ __half2 sW[16][264];    // k-pairs x 256 cols
    __shared__ __half  sC[32][264];    // 32-row staging
    int base0 = blockIdx.x * 128;
    int b     = blockIdx.y;
    int wid = threadIdx.x >> 5, lane = threadIdx.x & 31;
    int mw  = wid & 1;              // 0..1 : 32-row slab
    int nw  = wid >> 1;             // 0..7 : 32-col slab
    int gid = lane >> 2, qid = lane & 3;

    // load W slice for this b: 1024 uint4, 2 per thread (no cvt)
    const __half2* whb = wh + (size_t)b * 4096;
#pragma unroll
    for (int it = 0; it < 2; it++) {
        int idx = threadIdx.x + it * 512;   // [0, 1024)
        int c2 = idx >> 6, u = idx & 63;
        *(uint4*)&sW[c2][u * 4] = *(const uint4*)&whb[c2 * 256 + u * 4];
    }

#pragma unroll
    for (int t = 0; t < 2; t++) {
        int n0 = base0 + t * 64;
        // load A: 64x32 halves (256 uint4; first 256 threads)
        if (threadIdx.x < 256) {
            int node = threadIdx.x >> 2, k8 = (threadIdx.x & 3) * 8;
            uint4 v = make_uint4(0, 0, 0, 0);
            if (n0 + node < N0) v = *(const uint4*)&h[(size_t)(n0 + node) * HH + b * 32 + k8];
            *(uint2*)&sA[node][k8]     = make_uint2(v.x, v.y);
            *(uint2*)&sA[node][k8 + 4] = make_uint2(v.z, v.w);
        }
        __syncthreads();

        float c[2][4][4];
#pragma unroll
        for (int mt = 0; mt < 2; mt++)
#pragma unroll
            for (int nt = 0; nt < 4; nt++)
#pragma unroll
                for (int q = 0; q < 4; q++) c[mt][nt][q] = 0.f;

#pragma unroll
        for (int ks = 0; ks < 32; ks += 16) {
            uint32_t a[2][4], bb[4][2];
#pragma unroll
            for (int mt = 0; mt < 2; mt++) {
                int r = mw * 32 + mt * 16 + gid;
                a[mt][0] = *(const uint32_t*)&sA[r][ks + qid * 2];
                a[mt][1] = *(const uint32_t*)&sA[r + 8][ks + qid * 2];
                a[mt][2] = *(const uint32_t*)&sA[r][ks + qid * 2 + 8];
                a[mt][3] = *(const uint32_t*)&sA[r + 8][ks + qid * 2 + 8];
            }
            int kp = ks >> 1;
#pragma unroll
            for (int nt = 0; nt < 4; nt++) {
                int cn = nw * 32 + nt * 8 + gid;
                bb[nt][0] = *(const uint32_t*)&sW[kp + qid][cn];
                bb[nt][1] = *(const uint32_t*)&sW[kp + qid + 4][cn];
            }
#pragma unroll
            for (int mt = 0; mt < 2; mt++)
#pragma unroll
                for (int nt = 0; nt < 4; nt++) mma_f16(c[mt][nt], a[mt], bb[nt]);
        }

        // two-phase epilogue: stage 32 rows (warps with mw==hf), coalesced copy
#pragma unroll
        for (int hf = 0; hf < 2; hf++) {
            __syncthreads();   // MMA done (hf=0) / prior copy done (hf=1)
            if (mw == hf) {
#pragma unroll
                for (int mt = 0; mt < 2; mt++) {
                    int rl = mt * 16 + gid;   // local row within 32-half
#pragma unroll
                    for (int nt = 0; nt < 4; nt++) {
                        int col = nw * 32 + nt * 8 + qid * 2;
                        *(__half2*)&sC[rl][col]     = __floats2half2_rn(c[mt][nt][0], c[mt][nt][1]);
                        *(__half2*)&sC[rl + 8][col] = __floats2half2_rn(c[mt][nt][2], c[mt][nt][3]);
                    }
                }
            }
            __syncthreads();
            // copy: warp w handles rows w, w+16 (256 halves = 32 uint4 each)
            int rr = lane >> 2;          // relation 0..7
            int d8 = lane & 3;           // 8-half chunk within 32-d segment
#pragma unroll
            for (int it2 = 0; it2 < 2; it2++) {
                int rl = wid + it2 * 16;
                int node = n0 + hf * 32 + rl;
                if (node < N0) {
                    uint4 v = *(const uint4*)&sC[rl][rr * 32 + d8 * 8];
                    *(uint4*)&dst[((size_t)rr * N0 + node) * HH + b * 32 + d8 * 8] = v;
                }
            }
        }
        __syncthreads();   // sC/sA safe to reuse next subtile
    }
}

// ---------------------------------------------------------------------------
// Aggregation: one warp per dst, no atomics; folds final ReLU. Unroll 8 (MLP).
// out[dst] = relu(out[dst] + sum_e inv[r_e,dst] * txh[r_e][src_e])
// ---------------------------------------------------------------------------
__device__ __forceinline__ void agg_step(float4& acc, uint32_t pk,
                                         const float* __restrict__ inv,
                                         const __half* __restrict__ txh,
                                         int dst, int lane) {
    int r = pk >> 29;
    int s = pk & 0x1FFFFFFF;
    float w = __ldg(&inv[r * N0 + dst]);
    uint2 u = __ldg((const uint2*)&txh[((size_t)r * N0 + s) * HH + lane * 4]);
    float2 f01 = __half22float2(*(__half2*)&u.x);
    float2 f23 = __half22float2(*(__half2*)&u.y);
    acc.x += w * f01.x; acc.y += w * f01.y;
    acc.z += w * f23.x; acc.w += w * f23.y;
}

template <typename TO>
__global__ void agg_kernel(TO* __restrict__ out, const __half* __restrict__ txh,
                           const uint32_t* __restrict__ pl, const float* __restrict__ inv) {
    int wid  = (blockIdx.x * blockDim.x + threadIdx.x) >> 5;
    int lane = threadIdx.x & 31;
    if (wid >= N0) return;
    int o = g_off[wid];
    int n = g_deg[wid];

    float4 acc = make_float4(0.f, 0.f, 0.f, 0.f);
    int i = 0;
    for (; i + 8 <= n; i += 8) {
        uint32_t p[8];
#pragma unroll
        for (int u = 0; u < 8; u++) p[u] = __ldg(&pl[o + i + u]);
#pragma unroll
        for (int u = 0; u < 8; u++) agg_step(acc, p[u], inv, txh, wid, lane);
    }
    for (; i + 4 <= n; i += 4) {
        uint32_t p[4];
#pragma unroll
        for (int u = 0; u < 4; u++) p[u] = __ldg(&pl[o + i + u]);
#pragma unroll
        for (int u = 0; u < 4; u++) agg_step(acc, p[u], inv, txh, wid, lane);
    }
    for (; i < n; i++) {
        agg_step(acc, __ldg(&pl[o + i]), inv, txh, wid, lane);
    }

    if constexpr (std::is_same<TO, float>::value) {
        float* p = (float*)out + (size_t)wid * HH + lane * 4;
        float4 cur = *(float4*)p;
        cur.x = fmaxf(cur.x + acc.x, 0.f);
        cur.y = fmaxf(cur.y + acc.y, 0.f);
        cur.z = fmaxf(cur.z + acc.z, 0.f);
        cur.w = fmaxf(cur.w + acc.w, 0.f);
        *(float4*)p = cur;
    } else {
        __half* p = (__half*)out + (size_t)wid * HH + lane * 4;
        uint2 u = *(uint2*)p;
        float2 c01 = __half22float2(*(__half2*)&u.x);
        float2 c23 = __half22float2(*(__half2*)&u.y);
        __half2 o01 = __floats2half2_rn(fmaxf(c01.x + acc.x, 0.f), fmaxf(c01.y + acc.y, 0.f));
        __half2 o23 = __floats2half2_rn(fmaxf(c23.x + acc.z, 0.f), fmaxf(c23.y + acc.w, 0.f));
        uint2 w = make_uint2(*(uint32_t*)&o01, *(uint32_t*)&o23);
        *(uint2*)p = w;
    }
}

// ---------------------------------------------------------------------------
// Streams/events: 4-stream topology (known harness-clean).
// ---------------------------------------------------------------------------
namespace {
struct Ctx {
    cudaStream_t sc, sj[3];
    cudaEvent_t  eFork, eCsr, eH0, eA0[3], eDone[3];
    Ctx() {
        cudaStreamCreateWithFlags(&sc, cudaStreamNonBlocking);
        for (int i = 0; i < 3; i++) cudaStreamCreateWithFlags(&sj[i], cudaStreamNonBlocking);
        cudaEventCreateWithFlags(&eFork, cudaEventDisableTiming);
        cudaEventCreateWithFlags(&eCsr,  cudaEventDisableTiming);
        cudaEventCreateWithFlags(&eH0,   cudaEventDisableTiming);
        for (int i = 0; i < 3; i++) {
            cudaEventCreateWithFlags(&eA0[i],   cudaEventDisableTiming);
            cudaEventCreateWithFlags(&eDone[i], cudaEventDisableTiming);
        }
    }
};
Ctx g_ctx;  // constructed at load time
}

// ---------------------------------------------------------------------------
extern "C" void kernel_launch(void* const* d_in, const int* in_sizes, int n_in,
                              void* d_out, int out_size) {
    const float* x    = (const float*)d_in[0];   // (N0, 64)
    const int*   ei   = (const int*)d_in[1];     // (2, E)
    const int*   ea   = (const int*)d_in[2];     // (E, 3)
    const float* femb = (const float*)d_in[3];   // (64, 128)
    const float* cw   = (const float*)d_in[4];   // (2,3,8,4,32,32)
    const float* cr   = (const float*)d_in[5];   // (2,3,128,128)
    const float* cb   = (const float*)d_in[6];   // (2,3,128)
    float* out = (float*)d_out;                  // (180000, 128)

    __half *h0, *h1, *txbase;
    __half2* whb;
    float* invb;
    uint32_t* plb;
    cudaGetSymbolAddress((void**)&h0, g_h0);
    cudaGetSymbolAddress((void**)&h1, g_h1);
    cudaGetSymbolAddress((void**)&txbase, g_txh);
    cudaGetSymbolAddress((void**)&whb, g_wh);
    cudaGetSymbolAddress((void**)&invb, g_inv);
    cudaGetSymbolAddress((void**)&plb, g_plj);
    __half*   txb[3] = { txbase, txbase + TXSZ, txbase + 2 * TXSZ };
    uint32_t* plj[3] = { plb, plb + EE, plb + 2 * EE };
    float*    invj[3] = { invb, invb + RR * N0, invb + 2 * RR * N0 };

    const int NO_RELU    = 1 << 30;
    const int agg_blocks = (N0 * 32 + 255) / 256;   // warp per dst
    const int tx_blocks  = (N0 + 127) / 128;        // 128 nodes per block
    const int M1         = 3 * N0;                  // 60000

    Ctx& C = g_ctx;

    // ---- fork from the (captured) default stream ----
    cudaEventRecord(C.eFork, 0);
    cudaStreamWaitEvent(C.sc, C.eFork, 0);
    for (int j = 0; j < 3; j++) cudaStreamWaitEvent(C.sj[j], C.eFork, 0);

    // ---- weight fp16 precompute + femb gemm on sj[0]; eH0 orders both ----
    wcvt_kernel<<<(24 * 16 * 256 + 255) / 256, 256, 0, C.sj[0]>>>(cw);
    gemm_f16<float, __half><<<(N0 + 127) / 128, 512, 0, C.sj[0]>>>(
        x, femb, nullptr, h0, N0, 64, NO_RELU);
    cudaEventRecord(C.eH0, C.sj[0]);
    cudaStreamWaitEvent(C.sj[1], C.eH0, 0);
    cudaStreamWaitEvent(C.sj[2], C.eH0, 0);

    // ---- layer 0 tx + root gemms ----
    for (int j = 0; j < DD; j++) {
        const __half2* wh = whb + (size_t)(0 * DD + j) * 4 * 4096;
        tx_f16<<<dim3(tx_blocks, 4), 512, 0, C.sj[j]>>>(h0, wh, txb[j]);
    }
    for (int j = 0; j < DD; j++) {
        const float* root = cr + (size_t)(0 * DD + j) * (HH * HH);
        const float* bias = cb + (size_t)(0 * DD + j) * HH;
        __half* outr = h1 + (size_t)j * N0 * HH;
        gemm_f16<__half, __half><<<(N0 + 127) / 128, 512, 0, C.sj[j]>>>(
            h0, root, bias, outr, N0, HH, NO_RELU);
    }

    // ---- CSR + inverse counts on side stream (only agg depends on it) ----
    zero_kernel<<<(DD * RR * N0 + 255) / 256, 256, 0, C.sc>>>();
    count_kernel<<<(EE + 255) / 256, 256, 0, C.sc>>>(ei, ea);
    offsets_kernel<<<(N0 + 255) / 256, 256, 0, C.sc>>>();   // deg from counts (pre-inv)
    inv_kernel<<<(DD * RR * N0 + 255) / 256, 256, 0, C.sc>>>();
    fill_kernel<<<(EE + 255) / 256, 256, 0, C.sc>>>(ei, ea);
    cudaEventRecord(C.eCsr, C.sc);

    // ---- layer 0 agg (RMW on fp16 h1, folds relu; covers all N0 rows) ----
    for (int j = 0; j < DD; j++) {
        __half* outr = h1 + (size_t)j * N0 * HH;
        cudaStreamWaitEvent(C.sj[j], C.eCsr, 0);
        agg_kernel<__half><<<agg_blocks, 256, 0, C.sj[j]>>>(outr, txb[j], plj[j], invj[j]);
        cudaEventRecord(C.eA0[j], C.sj[j]);
    }

    // ---- layer 1 ----
    // tx reads h1 rows [0, N0) = layer-0 j=0 output -> start after eA0[0].
    for (int j = 0; j < DD; j++) {
        const __half2* wh = whb + (size_t)(1 * DD + j) * 4 * 4096;
        if (j != 0) cudaStreamWaitEvent(C.sj[j], C.eA0[0], 0);
        tx_f16<<<dim3(tx_blocks, 4), 512, 0, C.sj[j]>>>(h1, wh, txb[j]);
    }
    // root gemm needs the full h1 -> wait for the other two convs.
    for (int j = 0; j < DD; j++) {
        const float* root = cr + (size_t)(1 * DD + j) * (HH * HH);
        const float* bias = cb + (size_t)(1 * DD + j) * HH;
        float* outr = out + (size_t)j * M1 * HH;
        cudaStreamWaitEvent(C.sj[j], C.eA0[(j + 1) % 3], 0);
        cudaStreamWaitEvent(C.sj[j], C.eA0[(j + 2) % 3], 0);
        // rows >= N0 never receive agg: relu them in the gemm epilogue
        gemm_f16<__half, float><<<(M1 + 127) / 128, 512, 0, C.sj[j]>>>(
            h1, root, bias, outr, M1, HH, N0);
        agg_kernel<float><<<agg_blocks, 256, 0, C.sj[j]>>>(outr, txb[j], plj[j], invj[j]);
        cudaEventRecord(C.eDone[j], C.sj[j]);
    }

    // ---- join back to the default stream ----
    for (int j = 0; j < 3; j++) cudaStreamWaitEvent(0, C.eDone[j], 0);
}